// round 16
// baseline (speedup 1.0000x reference)
#include <cuda_runtime.h>
#include <cuda_fp16.h>
#include <cstdint>

#define N_NODES 8192
#define IN_DIM  256
#define OUT_DIM 128
#define NEG_SLOPE 0.2f
#define LOG2E 1.4426950408889634f

// ---------------- scratch (no allocations allowed) ----------------
__device__ float  g_ssrc[N_NODES];               // s_src * log2(e)  (fp32)
__device__ __half g_sdsth[N_NODES];              // s_dst * log2(e)  (fp16)
__device__ __half g_Whrm[N_NODES * OUT_DIM];     // Wh row-major fp16
__device__ float  g_part[2 * N_NODES * OUT_DIM]; // unnormalized partial outputs
__device__ float  g_rpart[2 * N_NODES];          // partial row sums

__device__ __forceinline__ uint32_t smem_u32(const void* p) {
    uint32_t a;
    asm("{ .reg .u64 t; cvta.to.shared.u64 t, %1; cvt.u32.u64 %0, t; }" : "=r"(a) : "l"(p));
    return a;
}
__device__ __forceinline__ void cp16(uint32_t dst, const void* src) {
    asm volatile("cp.async.cg.shared.global [%0], [%1], 16;" :: "r"(dst), "l"(src) : "memory");
}
#define CP_COMMIT() asm volatile("cp.async.commit_group;" ::: "memory")
#define CP_WAIT1()  asm volatile("cp.async.wait_group 1;" ::: "memory")

__device__ __forceinline__ uint32_t ex2_h2(uint32_t x) {
    uint32_t y; asm("ex2.approx.f16x2 %0, %1;" : "=r"(y) : "r"(x)); return y;
}

__device__ __forceinline__ void ldsm_x4(uint32_t& r0, uint32_t& r1, uint32_t& r2, uint32_t& r3,
                                        uint32_t addr) {
    asm volatile("ldmatrix.sync.aligned.m8n8.x4.shared.b16 {%0,%1,%2,%3}, [%4];"
                 : "=r"(r0), "=r"(r1), "=r"(r2), "=r"(r3) : "r"(addr));
}
__device__ __forceinline__ void ldsm_x4_t(uint32_t& r0, uint32_t& r1, uint32_t& r2, uint32_t& r3,
                                          uint32_t addr) {
    asm volatile("ldmatrix.sync.aligned.m8n8.x4.trans.shared.b16 {%0,%1,%2,%3}, [%4];"
                 : "=r"(r0), "=r"(r1), "=r"(r2), "=r"(r3) : "r"(addr));
}
__device__ __forceinline__ void mma_16816(float& c0, float& c1, float& c2, float& c3,
                                          uint32_t a0, uint32_t a1, uint32_t a2, uint32_t a3,
                                          uint32_t b0, uint32_t b1) {
    asm volatile("mma.sync.aligned.m16n8k16.row.col.f32.f16.f16.f32 "
                 "{%0,%1,%2,%3}, {%4,%5,%6,%7}, {%8,%9}, {%0,%1,%2,%3};"
                 : "+f"(c0), "+f"(c1), "+f"(c2), "+f"(c3)
                 : "r"(a0), "r"(a1), "r"(a2), "r"(a3), "r"(b0), "r"(b1));
}

// ---------------------------------------------------------------------------
// Kernel A: tiled fp32 GEMM. Block = 32 rows, 256 threads (better occupancy).
// Thread (ry,tx): rows ry*4..+4, cols tx*4..+4.
// ---------------------------------------------------------------------------
__global__ void __launch_bounds__(256) wh_kernel(const float* __restrict__ h,
                                                 const float* __restrict__ W,
                                                 const float* __restrict__ a) {
    __shared__ float hs[32 * 32];      // h chunk  [row][k]
    __shared__ float ws[32 * 128];     // W chunk  [k][col]

    const int r0  = blockIdx.x * 32;
    const int tid = threadIdx.x;
    const int tx  = tid & 31;
    const int ry  = tid >> 5;          // 0..7, rows ry*4..+4

    float acc[4][4];
#pragma unroll
    for (int i = 0; i < 4; ++i)
#pragma unroll
        for (int c = 0; c < 4; ++c) acc[i][c] = 0.f;

    for (int ck = 0; ck < 8; ++ck) {
        __syncthreads();
        // hs: 32x32 = 256 float4, 1 per thread
        {
            const int row = tid >> 3, kq = tid & 7;
            ((float4*)hs)[row * 8 + kq] =
                *(const float4*)(h + (size_t)(r0 + row) * IN_DIM + ck * 32 + kq * 4);
        }
        // ws: 32x128 = 1024 float4, 4 per thread
#pragma unroll
        for (int p = 0; p < 4; ++p) {
            const int idx = tid + p * 256;
            const int kr = idx >> 5, cq = idx & 31;
            ((float4*)ws)[kr * 32 + cq] =
                *(const float4*)(W + (size_t)(ck * 32 + kr) * OUT_DIM + cq * 4);
        }
        __syncthreads();
#pragma unroll 4
        for (int kk = 0; kk < 32; ++kk) {
            const float4 wv = ((const float4*)ws)[kk * 32 + tx];
#pragma unroll
            for (int i = 0; i < 4; ++i) {
                const float hv = hs[(ry * 4 + i) * 32 + kk];
                acc[i][0] = fmaf(hv, wv.x, acc[i][0]);
                acc[i][1] = fmaf(hv, wv.y, acc[i][1]);
                acc[i][2] = fmaf(hv, wv.z, acc[i][2]);
                acc[i][3] = fmaf(hv, wv.w, acc[i][3]);
            }
        }
    }

#pragma unroll
    for (int i = 0; i < 4; ++i) {
        const int row = r0 + ry * 4 + i;
        const __half2 lo = __floats2half2_rn(acc[i][0], acc[i][1]);
        const __half2 hi = __floats2half2_rn(acc[i][2], acc[i][3]);
        uint2 v;
        v.x = *(const uint32_t*)&lo;
        v.y = *(const uint32_t*)&hi;
        *(uint2*)(g_Whrm + (size_t)row * OUT_DIM + tx * 4) = v;
    }

    const float4 as4 = *(const float4*)(a + tx * 4);
    const float4 ad4 = *(const float4*)(a + OUT_DIM + tx * 4);
#pragma unroll
    for (int i = 0; i < 4; ++i) {
        float v1 = acc[i][0] * as4.x + acc[i][1] * as4.y + acc[i][2] * as4.z + acc[i][3] * as4.w;
        float v2 = acc[i][0] * ad4.x + acc[i][1] * ad4.y + acc[i][2] * ad4.z + acc[i][3] * ad4.w;
#pragma unroll
        for (int o = 16; o > 0; o >>= 1) {
            v1 += __shfl_xor_sync(0xFFFFFFFFu, v1, o);
            v2 += __shfl_xor_sync(0xFFFFFFFFu, v2, o);
        }
        if (tx == 0) {
            g_ssrc[r0 + ry * 4 + i]  = v1 * LOG2E;
            g_sdsth[r0 + ry * 4 + i] = __float2half(v2 * LOG2E);
        }
    }
}

// ---------------------------------------------------------------------------
// Kernel B: fused flash-GAT, j-split x2. 256 threads, 8 warps (2m x 4n of
// m32n32 -> 2 smem wavefronts per MMA). adj in regs; Bs 2-stage cp.async;
// up to 3 CTAs/SM. Writes UNNORMALIZED partials.
// ---------------------------------------------------------------------------
#define RT 64
#define KT 64
#define JH 4096
#define NT (JH / KT)

#define BS_ST(s)  ((s) * 16384)             // 2 x 16KB Bs [k][128 fp16] swizzled
#define AS_OFF(b) (32768 + (b) * 8192)      // 2 x 8KB  As [m][64 fp16] swizzled
#define SDALL_OFF 49152                     // 8KB sdst half (fp16)
#define SMEM_TOT  57344

#define ONES2 0x3C003C00u

__global__ void __launch_bounds__(256, 3) gat_kernel(const int* __restrict__ adj) {
    extern __shared__ char smem[];
    const uint32_t sb = smem_u32(smem);

    const int tid  = threadIdx.x;
    const int lane = tid & 31;
    const int wid  = tid >> 5;      // 0..7
    const int rb   = blockIdx.x & 127;
    const int half = blockIdx.x >> 7;
    const int i0   = rb * RT;
    const int j0   = half * JH;
    const int wm   = wid & 1;       // rows wm*32
    const int wn   = wid >> 1;      // cols wn*32

    const int prow = tid >> 2;      // 0..63
    const int q    = tid & 3;       // 16 j's at q*16
    const __half2 si2h   = __half2half2(__float2half(g_ssrc[i0 + prow]));
    const __half2 slope2 = __float2half2_rn(NEG_SLOPE);

    float acc[2][4][4];
#pragma unroll
    for (int m = 0; m < 2; ++m)
#pragma unroll
        for (int j = 0; j < 4; ++j)
#pragma unroll
            for (int k = 0; k < 4; ++k) acc[m][j][k] = 0.f;
    float accR[4] = {0.f, 0.f, 0.f, 0.f};   // ones rowsum: wn==0 -> mf0, wn==1 -> mf1

    const int l15 = lane & 15;
    const int lhi = lane >> 4;
    const uint32_t aswz    = (uint32_t)((l15 & 7) << 4);
    const uint32_t arowoff = (uint32_t)(wm * 32 + l15) * 128;

    const int* aptr = adj + (size_t)(i0 + prow) * N_NODES + j0 + q * 16;
    const uint32_t as_thr_off = (uint32_t)(prow * 128);

    auto issue = [&](int tt) {
        const uint32_t bb = sb + BS_ST(tt & 1);
#pragma unroll
        for (int p = 0; p < 4; ++p) {
            const int idx = tid + p * 256;
            const int br = idx >> 4;
            const int bg = idx & 15;
            cp16(bb + br * 256 + ((bg * 16) ^ ((br & 7) << 4)),
                 g_Whrm + (size_t)(j0 + tt * KT + br) * OUT_DIM + bg * 8);
        }
    };

    // P-phase: 16 elements per thread (2 x uint4)
    auto pphase = [&](int tt, int buf, const int4* pv) {
        char* asD = smem + AS_OFF(buf) + as_thr_off;
#pragma unroll
        for (int c = 0; c < 2; ++c) {
            const uint4 sjp = *(const uint4*)(smem + SDALL_OFF + tt * (KT * 2) + q * 32 + c * 16);
            const uint32_t sjv[4] = {sjp.x, sjp.y, sjp.z, sjp.w};
            const int4 av0 = pv[c * 2];
            const int4 av1 = pv[c * 2 + 1];
            uint32_t outv[4];
#pragma unroll
            for (int i = 0; i < 4; ++i) {
                const __half2 sj = *(const __half2*)&sjv[i];
                __half2 e = __hadd2(si2h, sj);
                e = __hmax2(e, __hmul2(e, slope2));
                uint32_t p = ex2_h2(*(const uint32_t*)&e);
                const int m0 = (i == 0) ? av0.x : (i == 1) ? av0.z : (i == 2) ? av1.x : av1.z;
                const int m1 = (i == 0) ? av0.y : (i == 1) ? av0.w : (i == 2) ? av1.y : av1.w;
                const uint32_t mask = (uint32_t)(m0 | (m1 << 16)) * 0x3C00u;
                const __half2 ph = __hmul2(*(const __half2*)&p, *(const __half2*)&mask);
                outv[i] = *(const uint32_t*)&ph;
            }
            uint4 st; st.x = outv[0]; st.y = outv[1]; st.z = outv[2]; st.w = outv[3];
            *(uint4*)(asD + ((q * 32 + c * 16) ^ ((prow & 7) << 4))) = st;
        }
    };

    // ---- prologue
    issue(0); CP_COMMIT();
    issue(1); CP_COMMIT();
    // stage this half's sdst: 4096 half = 512 uint4, 2 per thread
    {
        uint4* dst = (uint4*)(smem + SDALL_OFF);
        const uint4* src = (const uint4*)(g_sdsth + j0);
        dst[tid]       = src[tid];
        dst[tid + 256] = src[tid + 256];
    }
    int4 pv[4];
#pragma unroll
    for (int v = 0; v < 4; ++v) pv[v] = *(const int4*)(aptr + v * 4);
    __syncthreads();                 // sdst visible
    pphase(0, 0, pv);
#pragma unroll
    for (int v = 0; v < 4; ++v) pv[v] = *(const int4*)(aptr + KT + v * 4);
    __syncthreads();                 // As(0) visible

    int cur = 0;
    for (int t = 0; t < NT; ++t) {
        CP_WAIT1();                  // Bs slot t landed

        const uint32_t abase = sb + AS_OFF(cur) + arowoff;
        const uint32_t bbase = sb + BS_ST(t & 1) + (uint32_t)l15 * 256;
#pragma unroll
        for (int kf = 0; kf < 4; ++kf) {
            uint32_t a[2][4];
#pragma unroll
            for (int mf = 0; mf < 2; ++mf)
                ldsm_x4(a[mf][0], a[mf][1], a[mf][2], a[mf][3],
                        abase + (uint32_t)(mf * 16) * 128 +
                        (((uint32_t)(kf * 32 + lhi * 16)) ^ aswz));
            uint32_t b[4][2];
#pragma unroll
            for (int bf = 0; bf < 2; ++bf)
                ldsm_x4_t(b[bf * 2][0], b[bf * 2][1], b[bf * 2 + 1][0], b[bf * 2 + 1][1],
                          bbase + (uint32_t)(kf * 16) * 256 +
                          (((uint32_t)(wn * 64 + bf * 32 + lhi * 16)) ^ aswz));
#pragma unroll
            for (int mf = 0; mf < 2; ++mf)
#pragma unroll
                for (int nf = 0; nf < 4; ++nf)
                    mma_16816(acc[mf][nf][0], acc[mf][nf][1], acc[mf][nf][2], acc[mf][nf][3],
                              a[mf][0], a[mf][1], a[mf][2], a[mf][3],
                              b[nf][0], b[nf][1]);
            // ones rowsum: wn==0 warp covers its mf=0 rows, wn==1 covers mf=1
            if (wn < 2)
                mma_16816(accR[0], accR[1], accR[2], accR[3],
                          a[wn][0], a[wn][1], a[wn][2], a[wn][3], ONES2, ONES2);
        }

        if (t + 1 < NT) {
            pphase(t + 1, cur ^ 1, pv);
            if (t + 2 < NT) {
                const int* np = aptr + (size_t)(t + 2) * KT;
#pragma unroll
                for (int v = 0; v < 4; ++v) pv[v] = *(const int4*)(np + v * 4);
            }
        }
        __syncthreads();

        if (t + 2 < NT) issue(t + 2);
        CP_COMMIT();
        cur ^= 1;
    }

    // ---- partial row sums (wn 0/1 warps cover rows wm*32 + wn*16 ..)
    if (wn < 2 && (lane & 3) == 0) {
        const int r = wm * 32 + wn * 16 + (lane >> 2);
        g_rpart[half * N_NODES + i0 + r]     = accR[0];
        g_rpart[half * N_NODES + i0 + r + 8] = accR[2];
    }

    // ---- unnormalized partial outputs
    {
        float* base = g_part + (size_t)half * N_NODES * OUT_DIM;
#pragma unroll
        for (int mf = 0; mf < 2; ++mf) {
            const int rlo = wm * 32 + mf * 16 + (lane >> 2);
            const int rhi = rlo + 8;
            float* outlo = base + (size_t)(i0 + rlo) * OUT_DIM + wn * 32 + (lane & 3) * 2;
            float* outhi = base + (size_t)(i0 + rhi) * OUT_DIM + wn * 32 + (lane & 3) * 2;
#pragma unroll
            for (int nf = 0; nf < 4; ++nf) {
                float2 v;
                v.x = acc[mf][nf][0]; v.y = acc[mf][nf][1];
                *(float2*)(outlo + nf * 8) = v;
                v.x = acc[mf][nf][2]; v.y = acc[mf][nf][3];
                *(float2*)(outhi + nf * 8) = v;
            }
        }
    }
}

// ---------------------------------------------------------------------------
// Kernel C: combine halves + normalize.
// ---------------------------------------------------------------------------
__global__ void __launch_bounds__(512) norm_kernel(float* __restrict__ out) {
    const int idx = blockIdx.x * 512 + threadIdx.x;   // float4 index
    const int row = idx >> 5;                         // 32 float4 per row
    const float r = g_rpart[row] + g_rpart[N_NODES + row];
    const float inv = (r > 0.f) ? (1.f / r) : 0.f;
    const float4 p0 = ((const float4*)g_part)[idx];
    const float4 p1 = ((const float4*)(g_part + (size_t)N_NODES * OUT_DIM))[idx];
    float4 o;
    o.x = (p0.x + p1.x) * inv;
    o.y = (p0.y + p1.y) * inv;
    o.z = (p0.z + p1.z) * inv;
    o.w = (p0.w + p1.w) * inv;
    ((float4*)out)[idx] = o;
}

// ---------------------------------------------------------------------------
extern "C" void kernel_launch(void* const* d_in, const int* in_sizes, int n_in,
                              void* d_out, int out_size) {
    const float* h   = (const float*)d_in[0];   // [8192,256] f32
    const int*   adj = (const int*)  d_in[1];   // [8192,8192] i32
    const float* W   = (const float*)d_in[2];   // [256,128] f32
    const float* a   = (const float*)d_in[3];   // [256] f32
    float* out = (float*)d_out;                 // [8192,128] f32

    cudaFuncSetAttribute(gat_kernel, cudaFuncAttributeMaxDynamicSharedMemorySize, SMEM_TOT);

    wh_kernel<<<N_NODES / 32, 256>>>(h, W, a);
    gat_kernel<<<256, 256, SMEM_TOT>>>(adj);
    norm_kernel<<<(N_NODES * OUT_DIM / 4) / 512, 512>>>(out);
}

// round 17
// speedup vs baseline: 1.4663x; 1.4663x over previous
#include <cuda_runtime.h>
#include <cuda_fp16.h>
#include <cstdint>

#define N_NODES 8192
#define IN_DIM  256
#define OUT_DIM 128
#define NEG_SLOPE 0.2f
#define LOG2E 1.4426950408889634f

// ---------------- scratch (no allocations allowed) ----------------
__device__ float  g_ssrc[N_NODES];               // s_src * log2(e)  (fp32)
__device__ __half g_sdsth[N_NODES];              // s_dst * log2(e)  (fp16)
__device__ __half g_Whrm[N_NODES * OUT_DIM];     // Wh row-major fp16
__device__ float  g_part[2 * N_NODES * OUT_DIM]; // unnormalized partial outputs
__device__ float  g_rpart[2 * N_NODES];          // partial row sums

__device__ __forceinline__ uint32_t smem_u32(const void* p) {
    uint32_t a;
    asm("{ .reg .u64 t; cvta.to.shared.u64 t, %1; cvt.u32.u64 %0, t; }" : "=r"(a) : "l"(p));
    return a;
}
__device__ __forceinline__ void cp16(uint32_t dst, const void* src) {
    asm volatile("cp.async.cg.shared.global [%0], [%1], 16;" :: "r"(dst), "l"(src) : "memory");
}
#define CP_COMMIT() asm volatile("cp.async.commit_group;" ::: "memory")
#define CP_WAIT1()  asm volatile("cp.async.wait_group 1;" ::: "memory")

__device__ __forceinline__ uint32_t ex2_h2(uint32_t x) {
    uint32_t y; asm("ex2.approx.f16x2 %0, %1;" : "=r"(y) : "r"(x)); return y;
}

__device__ __forceinline__ void ldsm_x4(uint32_t& r0, uint32_t& r1, uint32_t& r2, uint32_t& r3,
                                        uint32_t addr) {
    asm volatile("ldmatrix.sync.aligned.m8n8.x4.shared.b16 {%0,%1,%2,%3}, [%4];"
                 : "=r"(r0), "=r"(r1), "=r"(r2), "=r"(r3) : "r"(addr));
}
__device__ __forceinline__ void ldsm_x4_t(uint32_t& r0, uint32_t& r1, uint32_t& r2, uint32_t& r3,
                                          uint32_t addr) {
    asm volatile("ldmatrix.sync.aligned.m8n8.x4.trans.shared.b16 {%0,%1,%2,%3}, [%4];"
                 : "=r"(r0), "=r"(r1), "=r"(r2), "=r"(r3) : "r"(addr));
}
__device__ __forceinline__ void mma_16816(float& c0, float& c1, float& c2, float& c3,
                                          uint32_t a0, uint32_t a1, uint32_t a2, uint32_t a3,
                                          uint32_t b0, uint32_t b1) {
    asm volatile("mma.sync.aligned.m16n8k16.row.col.f32.f16.f16.f32 "
                 "{%0,%1,%2,%3}, {%4,%5,%6,%7}, {%8,%9}, {%0,%1,%2,%3};"
                 : "+f"(c0), "+f"(c1), "+f"(c2), "+f"(c3)
                 : "r"(a0), "r"(a1), "r"(a2), "r"(a3), "r"(b0), "r"(b1));
}

// ---------------------------------------------------------------------------
// Kernel A (HMMA): Wh = h @ W on tensor cores. CTA = 32 rows x 128 cols,
// 256 threads, 8 warps (m32n16 each). K=256 in 4 chunks of 64, fp16 convert
// on load. Scores fused from fp32 accumulators.
// ---------------------------------------------------------------------------
__global__ void __launch_bounds__(256) wh_kernel(const float* __restrict__ h,
                                                 const float* __restrict__ W,
                                                 const float* __restrict__ a) {
    __shared__ char asmem[32 * 128];    // As: 32 rows x 64k fp16, swizzled
    __shared__ char bsmem[64 * 256];    // Bs: 64k x 128 cols fp16, swizzled
    __shared__ float av[2 * OUT_DIM];   // a vector
    __shared__ float sred[2 * 32 * 8];  // [score][row][warp]

    const int r0   = blockIdx.x * 32;
    const int tid  = threadIdx.x;
    const int lane = tid & 31;
    const int wn   = tid >> 5;          // warp -> cols wn*16

    av[tid] = a[tid];

    float acc[2][2][4];
#pragma unroll
    for (int m = 0; m < 2; ++m)
#pragma unroll
        for (int n = 0; n < 2; ++n)
#pragma unroll
            for (int c = 0; c < 4; ++c) acc[m][n][c] = 0.f;

    const int l15 = lane & 15;
    const int lhi = lane >> 4;
    const uint32_t aswz = (uint32_t)((l15 & 7) << 4);
    const uint32_t sbA = smem_u32(asmem);
    const uint32_t sbB = smem_u32(bsmem);

    for (int ck = 0; ck < 4; ++ck) {
        __syncthreads();
        // As: thread -> row tid>>3, 8 k's at (tid&7)*8
        {
            const int row = tid >> 3, kg = tid & 7;
            const float* src = h + (size_t)(r0 + row) * IN_DIM + ck * 64 + kg * 8;
            const float4 f0 = *(const float4*)(src);
            const float4 f1 = *(const float4*)(src + 4);
            const __half2 h0 = __floats2half2_rn(f0.x, f0.y);
            const __half2 h1 = __floats2half2_rn(f0.z, f0.w);
            const __half2 h2 = __floats2half2_rn(f1.x, f1.y);
            const __half2 h3 = __floats2half2_rn(f1.z, f1.w);
            uint4 st;
            st.x = *(const uint32_t*)&h0; st.y = *(const uint32_t*)&h1;
            st.z = *(const uint32_t*)&h2; st.w = *(const uint32_t*)&h3;
            *(uint4*)(asmem + row * 128 + ((kg * 16) ^ ((row & 7) << 4))) = st;
        }
        // Bs: 4 iters, idx -> k-row kr = idx>>4, 8 cols at (idx&15)*8
#pragma unroll
        for (int p = 0; p < 4; ++p) {
            const int idx = tid + p * 256;
            const int kr = idx >> 4, cg = idx & 15;
            const float* src = W + (size_t)(ck * 64 + kr) * OUT_DIM + cg * 8;
            const float4 f0 = *(const float4*)(src);
            const float4 f1 = *(const float4*)(src + 4);
            const __half2 h0 = __floats2half2_rn(f0.x, f0.y);
            const __half2 h1 = __floats2half2_rn(f0.z, f0.w);
            const __half2 h2 = __floats2half2_rn(f1.x, f1.y);
            const __half2 h3 = __floats2half2_rn(f1.z, f1.w);
            uint4 st;
            st.x = *(const uint32_t*)&h0; st.y = *(const uint32_t*)&h1;
            st.z = *(const uint32_t*)&h2; st.w = *(const uint32_t*)&h3;
            *(uint4*)(bsmem + kr * 256 + ((cg * 16) ^ ((kr & 7) << 4))) = st;
        }
        __syncthreads();

#pragma unroll
        for (int kf = 0; kf < 4; ++kf) {
            uint32_t af[2][4];
#pragma unroll
            for (int mf = 0; mf < 2; ++mf)
                ldsm_x4(af[mf][0], af[mf][1], af[mf][2], af[mf][3],
                        sbA + (uint32_t)(mf * 16 + l15) * 128 +
                        (((uint32_t)(kf * 32 + lhi * 16)) ^ aswz));
            uint32_t bf[4];
            ldsm_x4_t(bf[0], bf[1], bf[2], bf[3],
                      sbB + (uint32_t)(kf * 16 + l15) * 256 +
                      (((uint32_t)(wn * 32 + lhi * 16)) ^ aswz));
#pragma unroll
            for (int mf = 0; mf < 2; ++mf) {
                mma_16816(acc[mf][0][0], acc[mf][0][1], acc[mf][0][2], acc[mf][0][3],
                          af[mf][0], af[mf][1], af[mf][2], af[mf][3], bf[0], bf[1]);
                mma_16816(acc[mf][1][0], acc[mf][1][1], acc[mf][1][2], acc[mf][1][3],
                          af[mf][0], af[mf][1], af[mf][2], af[mf][3], bf[2], bf[3]);
            }
        }
    }

    // ---- store Wh fp16
#pragma unroll
    for (int mf = 0; mf < 2; ++mf) {
        const int rlo = mf * 16 + (lane >> 2);
        const int rhi = rlo + 8;
#pragma unroll
        for (int nf = 0; nf < 2; ++nf) {
            const int col = wn * 16 + nf * 8 + (lane & 3) * 2;
            const __half2 lo = __floats2half2_rn(acc[mf][nf][0], acc[mf][nf][1]);
            const __half2 hi = __floats2half2_rn(acc[mf][nf][2], acc[mf][nf][3]);
            *(uint32_t*)(g_Whrm + (size_t)(r0 + rlo) * OUT_DIM + col) = *(const uint32_t*)&lo;
            *(uint32_t*)(g_Whrm + (size_t)(r0 + rhi) * OUT_DIM + col) = *(const uint32_t*)&hi;
        }
    }

    // ---- fused scores
#pragma unroll
    for (int mf = 0; mf < 2; ++mf) {
        float v1lo = 0.f, v1hi = 0.f, v2lo = 0.f, v2hi = 0.f;
#pragma unroll
        for (int nf = 0; nf < 2; ++nf) {
            const int col = wn * 16 + nf * 8 + (lane & 3) * 2;
            const float a0s = av[col], a1s = av[col + 1];
            const float a0d = av[OUT_DIM + col], a1d = av[OUT_DIM + col + 1];
            v1lo += acc[mf][nf][0] * a0s + acc[mf][nf][1] * a1s;
            v1hi += acc[mf][nf][2] * a0s + acc[mf][nf][3] * a1s;
            v2lo += acc[mf][nf][0] * a0d + acc[mf][nf][1] * a1d;
            v2hi += acc[mf][nf][2] * a0d + acc[mf][nf][3] * a1d;
        }
#pragma unroll
        for (int o = 1; o < 4; o <<= 1) {
            v1lo += __shfl_xor_sync(0xFFFFFFFFu, v1lo, o);
            v1hi += __shfl_xor_sync(0xFFFFFFFFu, v1hi, o);
            v2lo += __shfl_xor_sync(0xFFFFFFFFu, v2lo, o);
            v2hi += __shfl_xor_sync(0xFFFFFFFFu, v2hi, o);
        }
        if ((lane & 3) == 0) {
            const int rlo = mf * 16 + (lane >> 2);
            sred[(0 * 32 + rlo) * 8 + wn]     = v1lo;
            sred[(0 * 32 + rlo + 8) * 8 + wn] = v1hi;
            sred[(1 * 32 + rlo) * 8 + wn]     = v2lo;
            sred[(1 * 32 + rlo + 8) * 8 + wn] = v2hi;
        }
    }
    __syncthreads();
    if (tid < 64) {
        const int row = tid >> 1, sc = tid & 1;
        const float* p = sred + (sc * 32 + row) * 8;
        float s = ((p[0] + p[1]) + (p[2] + p[3])) + ((p[4] + p[5]) + (p[6] + p[7]));
        s *= LOG2E;
        if (sc == 0) g_ssrc[r0 + row] = s;
        else         g_sdsth[r0 + row] = __float2half(s);
    }
}

// ---------------------------------------------------------------------------
// Kernel B: fused flash-GAT, j-split x2 (round-15 proven config, unchanged).
// 512 threads, 16 warps (4m x 4n of m16n32). adj in regs; Bs 2-stage
// cp.async; sdst half staged; ones-MMA row sums. UNNORMALIZED partials.
// ---------------------------------------------------------------------------
#define RT 64
#define KT 64
#define JH 4096
#define NT (JH / KT)

#define BS_ST(s)  ((s) * 16384)
#define AS_OFF(b) (32768 + (b) * 8192)
#define SDALL_OFF 49152
#define SMEM_TOT  57344

#define ONES2 0x3C003C00u

__global__ void __launch_bounds__(512, 2) gat_kernel(const int* __restrict__ adj) {
    extern __shared__ char smem[];
    const uint32_t sb = smem_u32(smem);

    const int tid  = threadIdx.x;
    const int lane = tid & 31;
    const int wid  = tid >> 5;
    const int rb   = blockIdx.x & 127;
    const int half = blockIdx.x >> 7;
    const int i0   = rb * RT;
    const int j0   = half * JH;
    const int wm   = wid & 3;
    const int wn   = wid >> 2;

    const int prow = tid >> 3;
    const int q    = tid & 7;
    const __half2 si2h   = __half2half2(__float2half(g_ssrc[i0 + prow]));
    const __half2 slope2 = __float2half2_rn(NEG_SLOPE);

    float acc[4][4];
#pragma unroll
    for (int j = 0; j < 4; ++j)
#pragma unroll
        for (int k = 0; k < 4; ++k) acc[j][k] = 0.f;
    float accR[4] = {0.f, 0.f, 0.f, 0.f};

    const int l15 = lane & 15;
    const int lhi = lane >> 4;
    const uint32_t aswz    = (uint32_t)((l15 & 7) << 4);
    const uint32_t arowoff = (uint32_t)(wm * 16 + l15) * 128;

    const int* aptr = adj + (size_t)(i0 + prow) * N_NODES + j0 + q * 8;
    const uint32_t as_thr_off = (uint32_t)(prow * 128);

    auto issue = [&](int tt) {
        const uint32_t bb = sb + BS_ST(tt & 1);
#pragma unroll
        for (int p = 0; p < 2; ++p) {
            const int idx = tid + p * 512;
            const int br = idx >> 4;
            const int bg = idx & 15;
            cp16(bb + br * 256 + ((bg * 16) ^ ((br & 7) << 4)),
                 g_Whrm + (size_t)(j0 + tt * KT + br) * OUT_DIM + bg * 8);
        }
    };

    auto pphase = [&](int tt, int buf, const int4& av0, const int4& av1) {
        const uint4 sjp = *(const uint4*)(smem + SDALL_OFF + tt * (KT * 2) + q * 16);
        const uint32_t sjv[4] = {sjp.x, sjp.y, sjp.z, sjp.w};
        uint32_t outv[4];
#pragma unroll
        for (int i = 0; i < 4; ++i) {
            const __half2 sj = *(const __half2*)&sjv[i];
            __half2 e = __hadd2(si2h, sj);
            e = __hmax2(e, __hmul2(e, slope2));
            uint32_t p = ex2_h2(*(const uint32_t*)&e);
            const int m0 = (i == 0) ? av0.x : (i == 1) ? av0.z : (i == 2) ? av1.x : av1.z;
            const int m1 = (i == 0) ? av0.y : (i == 1) ? av0.w : (i == 2) ? av1.y : av1.w;
            const uint32_t mask = (uint32_t)(m0 | (m1 << 16)) * 0x3C00u;
            const __half2 ph = __hmul2(*(const __half2*)&p, *(const __half2*)&mask);
            outv[i] = *(const uint32_t*)&ph;
        }
        uint4 st; st.x = outv[0]; st.y = outv[1]; st.z = outv[2]; st.w = outv[3];
        *(uint4*)(smem + AS_OFF(buf) + as_thr_off + ((q * 16) ^ ((prow & 7) << 4))) = st;
    };

    // ---- prologue
    issue(0); CP_COMMIT();
    issue(1); CP_COMMIT();
    {
        uint4* dst = (uint4*)(smem + SDALL_OFF);
        const uint4* src = (const uint4*)(g_sdsth + j0);
        if (tid < 512) dst[tid] = src[tid];
    }
    int4 pv0 = *(const int4*)(aptr);
    int4 pv1 = *(const int4*)(aptr + 4);
    __syncthreads();
    pphase(0, 0, pv0, pv1);
    pv0 = *(const int4*)(aptr + KT);
    pv1 = *(const int4*)(aptr + KT + 4);
    __syncthreads();

    int cur = 0;
    for (int t = 0; t < NT; ++t) {
        CP_WAIT1();

        const uint32_t abase = sb + AS_OFF(cur) + arowoff;
        const uint32_t bbase = sb + BS_ST(t & 1) + (uint32_t)l15 * 256;
#pragma unroll
        for (int kf = 0; kf < 4; ++kf) {
            uint32_t a[4];
            ldsm_x4(a[0], a[1], a[2], a[3],
                    abase + (((uint32_t)(kf * 32 + lhi * 16)) ^ aswz));
            uint32_t b[4][2];
#pragma unroll
            for (int bf = 0; bf < 2; ++bf)
                ldsm_x4_t(b[bf * 2][0], b[bf * 2][1], b[bf * 2 + 1][0], b[bf * 2 + 1][1],
                          bbase + (uint32_t)(kf * 16) * 256 +
                          (((uint32_t)(wn * 64 + bf * 32 + lhi * 16)) ^ aswz));
#pragma unroll
            for (int nf = 0; nf < 4; ++nf)
                mma_16816(acc[nf][0], acc[nf][1], acc[nf][2], acc[nf][3],
                          a[0], a[1], a[2], a[3], b[nf][0], b[nf][1]);
            if (wn == 0)
                mma_16816(accR[0], accR[1], accR[2], accR[3],
                          a[0], a[1], a[2], a[3], ONES2, ONES2);
        }

        if (t + 1 < NT) {
            pphase(t + 1, cur ^ 1, pv0, pv1);
            if (t + 2 < NT) {
                const int* np = aptr + (size_t)(t + 2) * KT;
                pv0 = *(const int4*)(np);
                pv1 = *(const int4*)(np + 4);
            }
        }
        __syncthreads();

        if (t + 2 < NT) issue(t + 2);
        CP_COMMIT();
        cur ^= 1;
    }

    if (wn == 0 && (lane & 3) == 0) {
        const int r = wm * 16 + (lane >> 2);
        g_rpart[half * N_NODES + i0 + r]     = accR[0];
        g_rpart[half * N_NODES + i0 + r + 8] = accR[2];
    }

    {
        const int rlo = wm * 16 + (lane >> 2);
        const int rhi = rlo + 8;
        float* base = g_part + (size_t)half * N_NODES * OUT_DIM;
        float* outlo = base + (size_t)(i0 + rlo) * OUT_DIM + wn * 32 + (lane & 3) * 2;
        float* outhi = base + (size_t)(i0 + rhi) * OUT_DIM + wn * 32 + (lane & 3) * 2;
#pragma unroll
        for (int nf = 0; nf < 4; ++nf) {
            float2 v;
            v.x = acc[nf][0]; v.y = acc[nf][1];
            *(float2*)(outlo + nf * 8) = v;
            v.x = acc[nf][2]; v.y = acc[nf][3];
            *(float2*)(outhi + nf * 8) = v;
        }
    }
}

// ---------------------------------------------------------------------------
// Kernel C: combine halves + normalize.
// ---------------------------------------------------------------------------
__global__ void __launch_bounds__(512) norm_kernel(float* __restrict__ out) {
    const int idx = blockIdx.x * 512 + threadIdx.x;
    const int row = idx >> 5;
    const float r = g_rpart[row] + g_rpart[N_NODES + row];
    const float inv = (r > 0.f) ? (1.f / r) : 0.f;
    const float4 p0 = ((const float4*)g_part)[idx];
    const float4 p1 = ((const float4*)(g_part + (size_t)N_NODES * OUT_DIM))[idx];
    float4 o;
    o.x = (p0.x + p1.x) * inv;
    o.y = (p0.y + p1.y) * inv;
    o.z = (p0.z + p1.z) * inv;
    o.w = (p0.w + p1.w) * inv;
    ((float4*)out)[idx] = o;
}

// ---------------------------------------------------------------------------
extern "C" void kernel_launch(void* const* d_in, const int* in_sizes, int n_in,
                              void* d_out, int out_size) {
    const float* h   = (const float*)d_in[0];   // [8192,256] f32
    const int*   adj = (const int*)  d_in[1];   // [8192,8192] i32
    const float* W   = (const float*)d_in[2];   // [256,128] f32
    const float* a   = (const float*)d_in[3];   // [256] f32
    float* out = (float*)d_out;                 // [8192,128] f32

    cudaFuncSetAttribute(gat_kernel, cudaFuncAttributeMaxDynamicSharedMemorySize, SMEM_TOT);

    wh_kernel<<<N_NODES / 32, 256>>>(h, W, a);
    gat_kernel<<<256, 512, SMEM_TOT>>>(adj);
    norm_kernel<<<(N_NODES * OUT_DIM / 4) / 512, 512>>>(out);
}